// round 5
// baseline (speedup 1.0000x reference)
#include <cuda_runtime.h>
#include <math.h>

#define N_POINTS 128
#define STEPS    50
#define N_EVENTS 10000
#define DT       2.0f
#define SQRT_PI_F 1.7724539f

#define N_PAIRS    ((N_POINTS * (N_POINTS - 1)) / 2)      // 8128
#define PAIR_TOTAL (N_PAIRS * STEPS)                      // 406400
#define TOTAL_WORK (PAIR_TOTAL + N_EVENTS)                // 416400

#define BLOCKS  592
#define THREADS 256
#define CHUNK   3                                         // 592*256*3 = 454656 >= TOTAL_WORK

// smem layout (floats): Z[256*50] | ts[51] | vl[50] | pad | 8 doubles
#define SM_Z     0
#define SM_TS    (2 * N_POINTS * STEPS)   // 12800
#define SM_VL    (SM_TS + STEPS + 1)      // 12851
#define SM_RED   (SM_VL + STEPS + 3)      // 12904 (8B aligned)
#define SMEM_FLOATS (SM_RED + 16)
#define SMEM_BYTES  (SMEM_FLOATS * 4)     // ~51.8 KB -> 4 blocks/SM

__device__ double       g_acc   = 0.0;
__device__ unsigned int g_count = 0;

__device__ __forceinline__ int tri_base(int i) {          // # pairs before row i
    return i * (N_POINTS - 1) - (i * (i - 1)) / 2;
}

// Abramowitz-Stegun 7.1.26: |err| < 1.5e-7
__device__ __forceinline__ float fast_erff(float x) {
    float ax = fabsf(x);
    float t  = __fdividef(1.0f, fmaf(0.3275911f, ax, 1.0f));
    float poly = t * fmaf(t, fmaf(t, fmaf(t, fmaf(t, 1.061405429f,
                    -1.453152027f), 1.421413741f), -0.284496736f), 0.254829592f);
    float r = 1.0f - poly * __expf(-ax * ax);
    return copysignf(r, x);
}

__global__ void __launch_bounds__(THREADS)
fused_kernel(const float* __restrict__ data,
             const float* __restrict__ beta,
             const float* __restrict__ z0,
             const float* __restrict__ v0,
             float* __restrict__ out) {
    extern __shared__ float sm[];
    float*  sZ  = sm + SM_Z;         // [row = point*2 + dim][s], stride 50
    float*  sTs = sm + SM_TS;        // ts[0..49]; slot 50 = times[M-1]
    float*  sVl = sm + SM_VL;
    double* sRd = (double*)(sm + SM_RED);

    const int   tid   = threadIdx.x;
    const float denom = DT + DT * 0.001f;                 // 2.002f, matches ref rounding
    const float b0    = __ldg(&beta[0]);

    // ---- per-block prep: search warps (tid 0..50) || cumsum threads (51..255) ----
    if (tid <= STEPS) {
        float tlast = __ldg(&data[(N_EVENTS - 1) * 3 + 2]);
        if (tid == STEPS) {
            sTs[STEPS] = tlast;                           // tf[49] = times[-1]
        } else {
            int s = tid, lo = 0, hi = N_EVENTS;           // first m with idx(t[m]) >= s
            while (lo < hi) {
                int mid = (lo + hi) >> 1;
                float t = __ldg(&data[mid * 3 + 2]);
                if ((int)floorf(t / denom) >= s) hi = mid; else lo = mid + 1;
            }
            float t  = (lo < N_EVENTS) ? __ldg(&data[lo * 3 + 2]) : 0.0f;
            int valid = (lo < N_EVENTS) && ((int)floorf(t / denom) == s);
            sTs[s] = valid ? t : tlast;                   // empty segment -> times[-1]
            sVl[s] = valid ? 1.0f : 0.0f;
        }
    } else {
        for (int r = tid - 51; r < 2 * N_POINTS; r += THREADS - 51) {
            float z = __ldg(&z0[r]);
            const float* vr = v0 + r * STEPS;
            float* Zr = sZ + r * STEPS;
            Zr[0] = z;                                    // Z_steps[0] = z0
            float cum = 0.0f;
            #pragma unroll
            for (int s = 1; s < STEPS; ++s) {
                cum += z + vr[s - 1] * DT;                // Z_steps[s]
                Zr[s] = cum;
            }
        }
    }
    __syncthreads();

    // ---- main phase: contiguous chunk of terms per thread ----
    double local = 0.0;
    int t0 = (blockIdx.x * THREADS + tid) * CHUNK;
    if (t0 < TOTAL_WORK) {
        int i = 0, j = 1, s = 0;
        if (t0 < PAIR_TOTAL) {                            // triangular decode + fixup
            int p = t0 / STEPS;
            s = t0 - p * STEPS;
            float disc = (float)(255 * 255 - 8 * p);
            i = (int)((255.0f - sqrtf(disc)) * 0.5f);
            i = min(max(i, 0), N_POINTS - 2);
            while (i < N_POINTS - 2 && tri_base(i + 1) <= p) ++i;
            while (i > 0 && tri_base(i) > p) --i;
            j = i + 1 + (p - tri_base(i));
        }

        #pragma unroll
        for (int k = 0; k < CHUNK; ++k) {
            int q = t0 + k;
            if (q >= TOTAL_WORK) break;
            if (q < PAIR_TOTAL) {
                int oi = i * 100 + s, oj = j * 100 + s;
                float dzx = sZ[oi]      - sZ[oj];
                float dzy = sZ[oi + 50] - sZ[oj + 50];
                float dvx = __ldg(&v0[oi])      - __ldg(&v0[oj]);
                float dvy = __ldg(&v0[oi + 50]) - __ldg(&v0[oj + 50]);

                float a = fmaxf(dvx * dvx + dvy * dvy, 1e-10f);
                float b = 2.0f * (dzx * dvx + dzy * dvy);
                float c = dzx * dzx + dzy * dzy;
                float rsa    = rsqrtf(a);
                float inv2sa = 0.5f * rsa;
                float shift  = b * inv2sa;
                float arg    = b0 - c + shift * shift;
                if (arg > -25.0f) {                       // exp-underflow skip
                    float sa = a * rsa;
                    float ts = sTs[s], tf = sTs[s + 1];
                    float loa = fmaf(sa, ts, shift);
                    float hia = fmaf(sa, tf, shift);
                    if (loa < 5.0f && hia > -5.0f) {      // erf-saturation skip
                        float pref  = SQRT_PI_F * inv2sa * __expf(arg);
                        float integ = pref * (fast_erff(hia) - fast_erff(loa));
                        local -= (double)(integ * sVl[s]);
                    }
                }
                if (++s == STEPS) {                       // advance (i,j,s)
                    s = 0;
                    if (++j == N_POINTS) { ++i; j = i + 1; }
                }
            } else {
                int e = q - PAIR_TOTAL;
                float si = data[e * 3], dj = data[e * 3 + 1], t = data[e * 3 + 2];
                int ii = (int)si, jj = (int)dj;
                float stepf = floorf(t / denom);
                int   id    = (int)stepf;
                float delta = t - stepf * DT;
                int oi = ii * 100 + id, oj = jj * 100 + id;
                float dx = (sZ[oi]      + __ldg(&v0[oi])      * delta)
                         - (sZ[oj]      + __ldg(&v0[oj])      * delta);
                float dy = (sZ[oi + 50] + __ldg(&v0[oi + 50]) * delta)
                         - (sZ[oj + 50] + __ldg(&v0[oj + 50]) * delta);
                local += (double)(b0 - (dx * dx + dy * dy));
            }
        }
    }

    // ---- reduction: warp shuffle -> smem -> warp0 -> global atomic ----
    double v = local;
    #pragma unroll
    for (int off = 16; off > 0; off >>= 1)
        v += __shfl_down_sync(0xffffffffu, v, off);
    int warp = tid >> 5, lane = tid & 31;
    if (lane == 0) sRd[warp] = v;
    __syncthreads();
    if (warp == 0) {
        v = (lane < THREADS / 32) ? sRd[lane] : 0.0;
        #pragma unroll
        for (int off = 4; off > 0; off >>= 1)
            v += __shfl_down_sync(0xffffffffu, v, off);
        if (lane == 0) {
            atomicAdd(&g_acc, v);
            __threadfence();
            unsigned int old = atomicAdd(&g_count, 1u);
            if (old == gridDim.x - 1) {
                double total = atomicAdd(&g_acc, 0.0);
                out[0] = (float)total;
                g_acc   = 0.0;                            // reset for next graph replay
                g_count = 0u;
            }
        }
    }
}

// Inputs (metadata order): data[30000], t0[1], tn[1], beta[1], z0[256], v0[12800]
extern "C" void kernel_launch(void* const* d_in, const int* in_sizes, int n_in,
                              void* d_out, int out_size) {
    const float* data = (const float*)d_in[0];
    const float* beta = (const float*)d_in[3];
    const float* z0   = (const float*)d_in[4];
    const float* v0   = (const float*)d_in[5];
    float* out = (float*)d_out;

    (void)cudaFuncSetAttribute(fused_kernel,
                               cudaFuncAttributeMaxDynamicSharedMemorySize,
                               SMEM_BYTES);
    fused_kernel<<<BLOCKS, THREADS, SMEM_BYTES>>>(data, beta, z0, v0, out);
}